// round 13
// baseline (speedup 1.0000x reference)
#include <cuda_runtime.h>

// N = 2^26 FFT of REAL fp32 input via half-length complex FFT (M = 2^25):
//   z[n] = x[2n] + i x[2n+1] (free reinterpret), Z = FFT_M(z), Hermitian unpack.
// Decomposition M = 256 * 512 * 256:
//   P1:  radix-256, s=1      z -> D   (d_out scratch)      [verified r7-r12]
//   P2:  radix-512, s=256    D -> B   (g_buf)              [verified r12]
//   P3U: radix-256 FINAL (ps=0, twiddle-free) fused with Hermitian unpack,
//        PIPELINED: 296 persistent-ish blocks x 512 thr, 3 x 33KB smem slots,
//        cp.async prefetch of pair i+1 overlaps FFT+unpack of pair i,
//        2 blocks/SM. B -> planar out.

#define NFFT  (1u << 26)
#define MFFT  (1u << 25)
#define M256  (1u << 17)   // MFFT/256
#define M512  (1u << 16)   // MFFT/512
#define SFIN  (1u << 17)   // final-pass stride s
#define NPAIR3 4097u
#define NGRID3 296u
#define SLOT  4128u        // one 256x16-group slot (float2), stride-258 layout
#define TWO_PI 6.28318530717958647692f
#define INVM  (1.0f / 33554432.0f)
#define INVN  (1.0f / 67108864.0f)

static __device__ float2 g_buf[MFFT];  // 256 MB scratch (sanctioned)

// exp(-2*pi*i*j/256), j = 0..15
__constant__ float2 c_w256[16] = {
    { 1.00000000000000000f, -0.00000000000000000f},
    { 0.99969881869620422f, -0.02454122852291229f},
    { 0.99879545620517241f, -0.04906767432741801f},
    { 0.99729045667869021f, -0.07356456359966743f},
    { 0.99518472667219693f, -0.09801714032956060f},
    { 0.99247953459870997f, -0.12241067519921620f},
    { 0.98917650996478101f, -0.14673047445536175f},
    { 0.98527764238894122f, -0.17096188876030122f},
    { 0.98078528040323044f, -0.19509032201612825f},
    { 0.97570213003852857f, -0.21910124015686980f},
    { 0.97003125319454397f, -0.24298017990326390f},
    { 0.96377606579543984f, -0.26671275747489837f},
    { 0.95694033573220882f, -0.29028467725446233f},
    { 0.94952818059303667f, -0.31368174039889152f},
    { 0.94154406518302081f, -0.33688985339222005f},
    { 0.93299279883473896f, -0.35989503653498817f}
};
// exp(-2*pi*i*k/32), k = 0..15
__constant__ float2 c_w32[16] = {
    { 1.00000000000000000f, -0.00000000000000000f},
    { 0.98078528040323045f, -0.19509032201612827f},
    { 0.92387953251128676f, -0.38268343236508977f},
    { 0.83146961230254524f, -0.55557023301960222f},
    { 0.70710678118654752f, -0.70710678118654752f},
    { 0.55557023301960222f, -0.83146961230254524f},
    { 0.38268343236508977f, -0.92387953251128676f},
    { 0.19509032201612827f, -0.98078528040323045f},
    { 0.00000000000000000f, -1.00000000000000000f},
    {-0.19509032201612827f, -0.98078528040323045f},
    {-0.38268343236508977f, -0.92387953251128676f},
    {-0.55557023301960222f, -0.83146961230254524f},
    {-0.70710678118654752f, -0.70710678118654752f},
    {-0.83146961230254524f, -0.55557023301960222f},
    {-0.92387953251128676f, -0.38268343236508977f},
    {-0.98078528040323045f, -0.19509032201612827f}
};

__device__ __forceinline__ float2 cmul(float2 a, float2 b) {
    return make_float2(a.x * b.x - a.y * b.y, a.x * b.y + a.y * b.x);
}
__device__ __forceinline__ float2 cadd(float2 a, float2 b) {
    return make_float2(a.x + b.x, a.y + b.y);
}
__device__ __forceinline__ float2 csub(float2 a, float2 b) {
    return make_float2(a.x - b.x, a.y - b.y);
}
__device__ __forceinline__ float2 cmul_negi(float2 a) { return make_float2(a.y, -a.x); }
__device__ __forceinline__ float2 cmul_posi(float2 a) { return make_float2(-a.y, a.x); }

// In-place forward DFT-16, natural order in/out (verified rounds 2-12).
__device__ __forceinline__ void dft16(float2 a[16]) {
    const float C1 = 0.92387953251128675613f;
    const float S1 = 0.38268343236508977173f;
    const float H  = 0.70710678118654752440f;
    const float2 W1 = make_float2( C1, -S1);
    const float2 W2 = make_float2(  H,  -H);
    const float2 W3 = make_float2( S1, -C1);
    const float2 W4 = make_float2(0.f, -1.f);
    const float2 W6 = make_float2( -H,  -H);
    const float2 W9 = make_float2(-C1,  S1);
    float2 b[16];
#pragma unroll
    for (int r1 = 0; r1 < 4; ++r1) {
        float2 x0 = a[r1], x1 = a[r1 + 4], x2 = a[r1 + 8], x3 = a[r1 + 12];
        float2 e = cadd(x0, x2), f = csub(x0, x2);
        float2 g = cadd(x1, x3), h = csub(x1, x3);
        b[r1 * 4 + 0] = cadd(e, g);
        b[r1 * 4 + 1] = cadd(f, cmul_negi(h));
        b[r1 * 4 + 2] = csub(e, g);
        b[r1 * 4 + 3] = cadd(f, cmul_posi(h));
    }
    b[5]  = cmul(b[5],  W1);
    b[6]  = cmul(b[6],  W2);
    b[7]  = cmul(b[7],  W3);
    b[9]  = cmul(b[9],  W2);
    b[10] = cmul(b[10], W4);
    b[11] = cmul(b[11], W6);
    b[13] = cmul(b[13], W3);
    b[14] = cmul(b[14], W6);
    b[15] = cmul(b[15], W9);
#pragma unroll
    for (int k1 = 0; k1 < 4; ++k1) {
        float2 x0 = b[k1], x1 = b[4 + k1], x2 = b[8 + k1], x3 = b[12 + k1];
        float2 e = cadd(x0, x2), f = csub(x0, x2);
        float2 g = cadd(x1, x3), h = csub(x1, x3);
        a[k1 + 0]  = cadd(e, g);
        a[k1 + 4]  = cadd(f, cmul_negi(h));
        a[k1 + 8]  = csub(e, g);
        a[k1 + 12] = cadd(f, cmul_posi(h));
    }
}

__device__ __forceinline__ unsigned swz(unsigned l) { return l + (l >> 8); }

// ---------------------------------------------------------------------------
// P1: radix-256, s=1, complex input (verified rounds 7-12, verbatim).
// ---------------------------------------------------------------------------
__global__ void __launch_bounds__(256) fft256_first(const float2* __restrict__ x,
                                                    float2* __restrict__ y) {
    __shared__ float2 sm[4112];
    unsigned tid = threadIdx.x;
    unsigned g = tid & 15u, j2 = tid >> 4;
    unsigned t = blockIdx.x * 16u + g;

    float2 a[16];
#pragma unroll
    for (int i = 0; i < 16; ++i) a[i] = x[t + (16u * (unsigned)i + j2) * M256];
    dft16(a);

    float sn, cs;
    __sincosf(-TWO_PI * (float)t * INVM, &sn, &cs);
    float2 wg = make_float2(cs, sn);
    float2 w1 = cmul(c_w256[j2], wg);
    float2 w = make_float2(1.f, 0.f);
#pragma unroll
    for (int k1 = 0; k1 < 16; ++k1) {
        sm[swz(tid + 256u * (unsigned)k1)] = cmul(a[k1], w);
        w = cmul(w, w1);
    }
    __syncthreads();

    unsigned k1p = tid >> 4;
#pragma unroll
    for (int j = 0; j < 16; ++j)
        a[j] = sm[swz(256u * k1p + 16u * (unsigned)j + g)];
    dft16(a);

    float2 w2 = cmul(wg, wg);
    w2 = cmul(w2, w2); w2 = cmul(w2, w2); w2 = cmul(w2, w2);  // wg^16
    float2 r[16];
    w = make_float2(1.f, 0.f);
#pragma unroll
    for (int k2 = 0; k2 < 16; ++k2) { r[k2] = cmul(a[k2], w); w = cmul(w, w2); }

    __syncthreads();
#pragma unroll
    for (int k2 = 0; k2 < 16; ++k2)
        sm[swz(256u * g + k1p + 16u * (unsigned)k2)] = r[k2];
    __syncthreads();

    unsigned base = blockIdx.x * 4096u;
#pragma unroll
    for (int i = 0; i < 16; ++i) {
        unsigned m = tid + 256u * (unsigned)i;
        y[base + m] = sm[swz(m)];
    }
}

// ---------------------------------------------------------------------------
// P2: radix-512 mid stage, s=256 (verified round 12, verbatim).
// ---------------------------------------------------------------------------
#define GS3 513u
__global__ void __launch_bounds__(512) fft512_mid(const float2* __restrict__ x,
                                                  float2* __restrict__ y) {
    extern __shared__ float2 smd[];
    const unsigned tid = threadIdx.x;
    const unsigned g = tid & 15u, u = tid >> 4;   // u in [0,32)
    const unsigned t = blockIdx.x * 16u + g;      // t in [0, 2^16)
    const unsigned gb = g * GS3;

    float2 a[16];
#pragma unroll
    for (int j = 0; j < 16; ++j) a[j] = x[t + (u + 32u * (unsigned)j) * M512];

    dft16(a);
    {
        float sn, cs;
        __sincosf(-TWO_PI * (float)u * (1.0f / 512.0f), &sn, &cs);
        float2 wa = make_float2(cs, sn), w = make_float2(1.f, 0.f);
#pragma unroll
        for (int k = 0; k < 16; ++k) {
            smd[gb + 16u * u + (unsigned)k] = cmul(a[k], w);
            w = cmul(w, wa);
        }
    }
    __syncthreads();

#pragma unroll
    for (int j = 0; j < 16; ++j) a[j] = smd[gb + u + 32u * (unsigned)j];
    dft16(a);
    __syncthreads();
    {
        unsigned q15 = u & 15u, p = u >> 4;
#pragma unroll
        for (int k = 0; k < 16; ++k) {
            float2 v = (p == 0u) ? a[k] : cmul(a[k], c_w32[k]);
            smd[gb + q15 + 256u * p + 16u * (unsigned)k] = v;
        }
    }
    __syncthreads();

    const unsigned q = t & 255u;
    const unsigned ps = t - q;
    const float fps = (float)ps;
    float2 Wu, W32, W256;
    { float sn, cs; __sincosf(-TWO_PI * (fps * (float)u) * INVM, &sn, &cs); Wu   = make_float2(cs, sn); }
    { float sn, cs; __sincosf(-TWO_PI * (fps * 32.0f) * INVM, &sn, &cs);    W32  = make_float2(cs, sn); }
    { float sn, cs; __sincosf(-TWO_PI * (fps * 256.0f) * INVM, &sn, &cs);   W256 = make_float2(cs, sn); }

    const unsigned base = q + (ps << 9);
    float2 w = Wu;
#pragma unroll
    for (int i = 0; i < 8; ++i) {
        unsigned t2 = u + 32u * (unsigned)i;
        float2 b0 = smd[gb + t2];
        float2 b1 = smd[gb + t2 + 256u];
        float2 v0 = cadd(b0, b1);
        float2 v1 = csub(b0, b1);
        y[base + (t2 << 8)]           = cmul(v0, w);
        y[base + ((t2 + 256u) << 8)]  = cmul(v1, cmul(w, W256));
        w = cmul(w, W32);
    }
}

// ----------------------------- cp.async helpers -----------------------------
__device__ __forceinline__ void cp_async8(void* smem_dst, const void* gmem_src) {
    unsigned d = (unsigned)__cvta_generic_to_shared(smem_dst);
    asm volatile("cp.async.ca.shared.global [%0], [%1], 8;\n" :: "r"(d), "l"(gmem_src));
}
__device__ __forceinline__ void cp_commit() {
    asm volatile("cp.async.commit_group;\n");
}
__device__ __forceinline__ void cp_wait1() {
    asm volatile("cp.async.wait_group 1;\n");
}
__device__ __forceinline__ void cp_wait0() {
    asm volatile("cp.async.wait_group 0;\n");
}

// ---------------------------------------------------------------------------
// P3U pipelined: final radix-256 (ps=0) fused with Hermitian unpack.
// Slot raw/Z layout: sm[slot*SLOT + g*258 + r]  (bank 2g+r: conflict-free
// for load, layer-1 read, Z write, unpack reads).  Staging uses swz().
// Pair p: half A = groups tA = 16p+g; half B = mirrors
// tB = (SFIN - 16p - 15 + g) mod SFIN (group 15-g mirrors g; t=0 self-mirror
// with k' = (256-k) mod 256). Grid 296, each block loops p += 296.
// ---------------------------------------------------------------------------
__device__ __forceinline__ void p3_load_half(const float2* __restrict__ x,
                                             float2* __restrict__ sm,
                                             unsigned slot, unsigned p, int half,
                                             unsigned lg, unsigned lu) {
    unsigned t = half ? ((SFIN - 16u * p - 15u + lg) & (SFIN - 1u))
                      : (16u * p + lg);
    float2* dst = sm + slot * SLOT + lg * 258u;
#pragma unroll
    for (int j = 0; j < 8; ++j) {
        unsigned r = lu + 32u * (unsigned)j;
        cp_async8(dst + r, x + t + r * SFIN);
    }
}

__global__ void __launch_bounds__(512, 2) fft256_unpack_pipe(
        const float2* __restrict__ x, float* __restrict__ out) {
    extern __shared__ float2 sm[];
    const unsigned tid = threadIdx.x;
    const unsigned lg = tid & 15u, lu = tid >> 4;      // load map: lu in [0,32)
    const unsigned half = tid >> 8;                    // FFT map
    const unsigned ltid = tid & 255u;
    const unsigned g = ltid & 15u, j2 = ltid >> 4;
    const unsigned k1p = ltid >> 4;

    unsigned p = blockIdx.x;
    // Prologue: stream both halves of the first pair.
    p3_load_half(x, sm, 0u, p, 0, lg, lu); cp_commit();
    p3_load_half(x, sm, 1u, p, 1, lg, lu); cp_commit();
    unsigned sA = 0u, sB = 1u, sF = 2u;

    for (;;) {
        unsigned pn = p + NGRID3;
        bool has_next = (pn < NPAIR3);
        if (has_next) { p3_load_half(x, sm, sF, pn, 0, lg, lu); cp_commit(); }

        if (has_next) cp_wait1(); else cp_wait0();
        __syncthreads();  // current pair's raw data visible

        // ---- FFT phase: both halves in parallel (ps=0 -> no outer twiddle) ----
        {
            float2* gb = sm + (half ? sB : sA) * SLOT;
            float2 a[16];
#pragma unroll
            for (int i = 0; i < 16; ++i)
                a[i] = gb[g * 258u + 16u * (unsigned)i + j2];
            dft16(a);
            __syncthreads();  // raw reads done before staging overwrite
            {
                float2 w1 = c_w256[j2], w = make_float2(1.f, 0.f);
#pragma unroll
                for (int k1 = 0; k1 < 16; ++k1) {
                    gb[swz(ltid + 256u * (unsigned)k1)] = cmul(a[k1], w);
                    w = cmul(w, w1);
                }
            }
            __syncthreads();
#pragma unroll
            for (int j = 0; j < 16; ++j)
                a[j] = gb[swz(256u * k1p + 16u * (unsigned)j + g)];
            dft16(a);
            __syncthreads();  // staging reads done before Z overwrite
#pragma unroll
            for (int k2 = 0; k2 < 16; ++k2)
                gb[g * 258u + k1p + 16u * (unsigned)k2] = a[k2];
        }
        __syncthreads();  // Z visible for cross-half unpack reads

        // ---- unpack phase (512 threads, 8 k's each; r8/r12-verified) ----
        {
            const unsigned gA = tid & 15u;
            const unsigned uu = tid >> 4;            // [0, 32)
            const unsigned t3 = 16u * p + gA;        // A-group t (< SFIN)
            const float2* gbA = sm + sA * SLOT + gA * 258u;
            const float2* gbB = sm + sB * SLOT + (15u - gA) * 258u;
            const bool tzero = (t3 == 0u);

            float sn, cs;
            __sincosf(-TWO_PI * (float)(t3 + uu * SFIN) * INVN, &sn, &cs);
            float2 W = make_float2(cs, sn);
            const float2 Winc = c_w32[2];            // e^{-2pi i/16}: k += 32

#pragma unroll
            for (int j = 0; j < 8; ++j) {
                unsigned k = uu + 32u * (unsigned)j;
                float2 Zk = gbA[k];
                unsigned kp = tzero ? ((256u - k) & 255u) : (255u - k);
                float2 Zm = gbB[kp];

                float2 A = make_float2(0.5f * (Zk.x + Zm.x), 0.5f * (Zk.y - Zm.y));
                float2 C = make_float2(0.5f * (Zk.x - Zm.x), 0.5f * (Zk.y + Zm.y));
                float2 B = make_float2(C.y, -C.x);
                float2 WB = cmul(W, B);
                float2 P = cadd(A, WB);
                float2 Q = csub(A, WB);

                unsigned m = t3 + k * SFIN;              // [0, M)
                unsigned i3 = (NFFT - m) & (NFFT - 1u);  // N - m (mod N)
                unsigned i2 = MFFT - m;
                unsigned i4 = MFFT + m;

                out[m]  = P.x;   out[NFFT + m]  = P.y;
                out[i3] = P.x;   out[NFFT + i3] = -P.y;
                out[i2] = Q.x;   out[NFFT + i2] = -Q.y;
                out[i4] = Q.x;   out[NFFT + i4] = Q.y;

                W = cmul(W, Winc);
            }
        }
        __syncthreads();  // unpack reads done before slot sA is refilled

        if (!has_next) break;
        p3_load_half(x, sm, sA, pn, 1, lg, lu); cp_commit();  // B(pn) -> freed sA

        unsigned oldA = sA;
        sA = sF;      // holds A(pn)
        sF = sB;      // free; receives A(pn+NGRID3) next iteration
        sB = oldA;    // receiving B(pn)
        p = pn;
    }
}

// ---------------------------------------------------------------------------
// Schedule: P1: z -> D (d_out scratch); P2: D -> B (g_buf); P3U: B -> out.
// P3U reads only g_buf, writes only d_out: no aliasing hazard.
// ---------------------------------------------------------------------------
extern "C" void kernel_launch(void* const* d_in, const int* in_sizes, int n_in,
                              void* d_out, int out_size) {
    const float2* z = (const float2*)d_in[0];   // N reals = M complex (free pack)
    float* out = (float*)d_out;
    float2* D = (float2*)d_out;                 // M float2 scratch fits in out
    float2* B = nullptr;
    cudaGetSymbolAddress((void**)&B, g_buf);

    const size_t smem2 = (size_t)(16u * GS3) * sizeof(float2);  // 65,664 B
    const size_t smem3 = (size_t)(3u * SLOT) * sizeof(float2);  // 99,072 B
    cudaFuncSetAttribute(fft512_mid,
                         cudaFuncAttributeMaxDynamicSharedMemorySize, (int)smem2);
    cudaFuncSetAttribute(fft256_unpack_pipe,
                         cudaFuncAttributeMaxDynamicSharedMemorySize, (int)smem3);

    fft256_first    <<<M256 / 16u, 256>>>(z, D);           // 8192 blocks
    fft512_mid      <<<M512 / 16u, 512, smem2>>>(D, B);    // 4096 blocks
    fft256_unpack_pipe<<<NGRID3, 512, smem3>>>(B, out);    // 296 blocks
}

// round 14
// speedup vs baseline: 1.0243x; 1.0243x over previous
#include <cuda_runtime.h>

// N = 2^26 FFT of REAL fp32 input via half-length complex FFT (M = 2^25):
//   z[n] = x[2n] + i x[2n+1] (free reinterpret), Z = FFT_M(z), Hermitian unpack.
// Decomposition M = 256 * 512 * 256:
//   P1:  radix-256, s=1      z -> D   (d_out scratch)      [verified r7-r13]
//   P2:  radix-512, s=256    D -> B   (g_buf)              [verified r12-r13]
//   P3U: radix-256 FINAL (ps=0) fused with Hermitian unpack, WARP-AUTONOMOUS:
//        each warp FFTs its 2 groups in a private smem region with only
//        __syncwarp(); ONE __syncthreads before unpack. 512 thr, 70KB smem,
//        2 blocks/SM, 4097 blocks. B -> planar out.

#define NFFT  (1u << 26)
#define MFFT  (1u << 25)
#define M256  (1u << 17)   // MFFT/256
#define M512  (1u << 16)   // MFFT/512
#define SFIN  (1u << 17)   // final-pass stride s
#define NPAIR3 4097u
#define REGION 273u        // per-group smem region (float2); 16x17 layout + pad
#define TWO_PI 6.28318530717958647692f
#define INVM  (1.0f / 33554432.0f)
#define INVN  (1.0f / 67108864.0f)

static __device__ float2 g_buf[MFFT];  // 256 MB scratch (sanctioned)

// exp(-2*pi*i*j/256), j = 0..15
__constant__ float2 c_w256[16] = {
    { 1.00000000000000000f, -0.00000000000000000f},
    { 0.99969881869620422f, -0.02454122852291229f},
    { 0.99879545620517241f, -0.04906767432741801f},
    { 0.99729045667869021f, -0.07356456359966743f},
    { 0.99518472667219693f, -0.09801714032956060f},
    { 0.99247953459870997f, -0.12241067519921620f},
    { 0.98917650996478101f, -0.14673047445536175f},
    { 0.98527764238894122f, -0.17096188876030122f},
    { 0.98078528040323044f, -0.19509032201612825f},
    { 0.97570213003852857f, -0.21910124015686980f},
    { 0.97003125319454397f, -0.24298017990326390f},
    { 0.96377606579543984f, -0.26671275747489837f},
    { 0.95694033573220882f, -0.29028467725446233f},
    { 0.94952818059303667f, -0.31368174039889152f},
    { 0.94154406518302081f, -0.33688985339222005f},
    { 0.93299279883473896f, -0.35989503653498817f}
};
// exp(-2*pi*i*k/32), k = 0..15
__constant__ float2 c_w32[16] = {
    { 1.00000000000000000f, -0.00000000000000000f},
    { 0.98078528040323045f, -0.19509032201612827f},
    { 0.92387953251128676f, -0.38268343236508977f},
    { 0.83146961230254524f, -0.55557023301960222f},
    { 0.70710678118654752f, -0.70710678118654752f},
    { 0.55557023301960222f, -0.83146961230254524f},
    { 0.38268343236508977f, -0.92387953251128676f},
    { 0.19509032201612827f, -0.98078528040323045f},
    { 0.00000000000000000f, -1.00000000000000000f},
    {-0.19509032201612827f, -0.98078528040323045f},
    {-0.38268343236508977f, -0.92387953251128676f},
    {-0.55557023301960222f, -0.83146961230254524f},
    {-0.70710678118654752f, -0.70710678118654752f},
    {-0.83146961230254524f, -0.55557023301960222f},
    {-0.92387953251128676f, -0.38268343236508977f},
    {-0.98078528040323045f, -0.19509032201612827f}
};

__device__ __forceinline__ float2 cmul(float2 a, float2 b) {
    return make_float2(a.x * b.x - a.y * b.y, a.x * b.y + a.y * b.x);
}
__device__ __forceinline__ float2 cadd(float2 a, float2 b) {
    return make_float2(a.x + b.x, a.y + b.y);
}
__device__ __forceinline__ float2 csub(float2 a, float2 b) {
    return make_float2(a.x - b.x, a.y - b.y);
}
__device__ __forceinline__ float2 cmul_negi(float2 a) { return make_float2(a.y, -a.x); }
__device__ __forceinline__ float2 cmul_posi(float2 a) { return make_float2(-a.y, a.x); }

// In-place forward DFT-16, natural order in/out (verified rounds 2-13).
__device__ __forceinline__ void dft16(float2 a[16]) {
    const float C1 = 0.92387953251128675613f;
    const float S1 = 0.38268343236508977173f;
    const float H  = 0.70710678118654752440f;
    const float2 W1 = make_float2( C1, -S1);
    const float2 W2 = make_float2(  H,  -H);
    const float2 W3 = make_float2( S1, -C1);
    const float2 W4 = make_float2(0.f, -1.f);
    const float2 W6 = make_float2( -H,  -H);
    const float2 W9 = make_float2(-C1,  S1);
    float2 b[16];
#pragma unroll
    for (int r1 = 0; r1 < 4; ++r1) {
        float2 x0 = a[r1], x1 = a[r1 + 4], x2 = a[r1 + 8], x3 = a[r1 + 12];
        float2 e = cadd(x0, x2), f = csub(x0, x2);
        float2 g = cadd(x1, x3), h = csub(x1, x3);
        b[r1 * 4 + 0] = cadd(e, g);
        b[r1 * 4 + 1] = cadd(f, cmul_negi(h));
        b[r1 * 4 + 2] = csub(e, g);
        b[r1 * 4 + 3] = cadd(f, cmul_posi(h));
    }
    b[5]  = cmul(b[5],  W1);
    b[6]  = cmul(b[6],  W2);
    b[7]  = cmul(b[7],  W3);
    b[9]  = cmul(b[9],  W2);
    b[10] = cmul(b[10], W4);
    b[11] = cmul(b[11], W6);
    b[13] = cmul(b[13], W3);
    b[14] = cmul(b[14], W6);
    b[15] = cmul(b[15], W9);
#pragma unroll
    for (int k1 = 0; k1 < 4; ++k1) {
        float2 x0 = b[k1], x1 = b[4 + k1], x2 = b[8 + k1], x3 = b[12 + k1];
        float2 e = cadd(x0, x2), f = csub(x0, x2);
        float2 g = cadd(x1, x3), h = csub(x1, x3);
        a[k1 + 0]  = cadd(e, g);
        a[k1 + 4]  = cadd(f, cmul_negi(h));
        a[k1 + 8]  = csub(e, g);
        a[k1 + 12] = cadd(f, cmul_posi(h));
    }
}

__device__ __forceinline__ unsigned swz(unsigned l) { return l + (l >> 8); }

// ---------------------------------------------------------------------------
// P1: radix-256, s=1, complex input (verified rounds 7-13, verbatim).
// ---------------------------------------------------------------------------
__global__ void __launch_bounds__(256) fft256_first(const float2* __restrict__ x,
                                                    float2* __restrict__ y) {
    __shared__ float2 sm[4112];
    unsigned tid = threadIdx.x;
    unsigned g = tid & 15u, j2 = tid >> 4;
    unsigned t = blockIdx.x * 16u + g;

    float2 a[16];
#pragma unroll
    for (int i = 0; i < 16; ++i) a[i] = x[t + (16u * (unsigned)i + j2) * M256];
    dft16(a);

    float sn, cs;
    __sincosf(-TWO_PI * (float)t * INVM, &sn, &cs);
    float2 wg = make_float2(cs, sn);
    float2 w1 = cmul(c_w256[j2], wg);
    float2 w = make_float2(1.f, 0.f);
#pragma unroll
    for (int k1 = 0; k1 < 16; ++k1) {
        sm[swz(tid + 256u * (unsigned)k1)] = cmul(a[k1], w);
        w = cmul(w, w1);
    }
    __syncthreads();

    unsigned k1p = tid >> 4;
#pragma unroll
    for (int j = 0; j < 16; ++j)
        a[j] = sm[swz(256u * k1p + 16u * (unsigned)j + g)];
    dft16(a);

    float2 w2 = cmul(wg, wg);
    w2 = cmul(w2, w2); w2 = cmul(w2, w2); w2 = cmul(w2, w2);  // wg^16
    float2 r[16];
    w = make_float2(1.f, 0.f);
#pragma unroll
    for (int k2 = 0; k2 < 16; ++k2) { r[k2] = cmul(a[k2], w); w = cmul(w, w2); }

    __syncthreads();
#pragma unroll
    for (int k2 = 0; k2 < 16; ++k2)
        sm[swz(256u * g + k1p + 16u * (unsigned)k2)] = r[k2];
    __syncthreads();

    unsigned base = blockIdx.x * 4096u;
#pragma unroll
    for (int i = 0; i < 16; ++i) {
        unsigned m = tid + 256u * (unsigned)i;
        y[base + m] = sm[swz(m)];
    }
}

// ---------------------------------------------------------------------------
// P2: radix-512 mid stage, s=256 (verified rounds 12-13, verbatim).
// ---------------------------------------------------------------------------
#define GS3 513u
__global__ void __launch_bounds__(512) fft512_mid(const float2* __restrict__ x,
                                                  float2* __restrict__ y) {
    extern __shared__ float2 smd[];
    const unsigned tid = threadIdx.x;
    const unsigned g = tid & 15u, u = tid >> 4;   // u in [0,32)
    const unsigned t = blockIdx.x * 16u + g;      // t in [0, 2^16)
    const unsigned gb = g * GS3;

    float2 a[16];
#pragma unroll
    for (int j = 0; j < 16; ++j) a[j] = x[t + (u + 32u * (unsigned)j) * M512];

    dft16(a);
    {
        float sn, cs;
        __sincosf(-TWO_PI * (float)u * (1.0f / 512.0f), &sn, &cs);
        float2 wa = make_float2(cs, sn), w = make_float2(1.f, 0.f);
#pragma unroll
        for (int k = 0; k < 16; ++k) {
            smd[gb + 16u * u + (unsigned)k] = cmul(a[k], w);
            w = cmul(w, wa);
        }
    }
    __syncthreads();

#pragma unroll
    for (int j = 0; j < 16; ++j) a[j] = smd[gb + u + 32u * (unsigned)j];
    dft16(a);
    __syncthreads();
    {
        unsigned q15 = u & 15u, p = u >> 4;
#pragma unroll
        for (int k = 0; k < 16; ++k) {
            float2 v = (p == 0u) ? a[k] : cmul(a[k], c_w32[k]);
            smd[gb + q15 + 256u * p + 16u * (unsigned)k] = v;
        }
    }
    __syncthreads();

    const unsigned q = t & 255u;
    const unsigned ps = t - q;
    const float fps = (float)ps;
    float2 Wu, W32, W256;
    { float sn, cs; __sincosf(-TWO_PI * (fps * (float)u) * INVM, &sn, &cs); Wu   = make_float2(cs, sn); }
    { float sn, cs; __sincosf(-TWO_PI * (fps * 32.0f) * INVM, &sn, &cs);    W32  = make_float2(cs, sn); }
    { float sn, cs; __sincosf(-TWO_PI * (fps * 256.0f) * INVM, &sn, &cs);   W256 = make_float2(cs, sn); }

    const unsigned base = q + (ps << 9);
    float2 w = Wu;
#pragma unroll
    for (int i = 0; i < 8; ++i) {
        unsigned t2 = u + 32u * (unsigned)i;
        float2 b0 = smd[gb + t2];
        float2 b1 = smd[gb + t2 + 256u];
        float2 v0 = cadd(b0, b1);
        float2 v1 = csub(b0, b1);
        y[base + (t2 << 8)]           = cmul(v0, w);
        y[base + ((t2 + 256u) << 8)]  = cmul(v1, cmul(w, W256));
        w = cmul(w, W32);
    }
}

// ---------------------------------------------------------------------------
// P3U warp-autonomous: final radix-256 (ps=0, twiddle-free outer) fused with
// Hermitian unpack. Block = 512 thr = 16 warps; warp w owns 2 groups in
// private smem regions (units 2(w&7)+lt; warps 0-7 = A half, 8-15 = B half).
//   A group gA:  t = 16b + gA
//   B group g':  t = (SFIN - 16b - 15 + g') mod SFIN  (mirror of gA is 15-gA)
// Per warp (only __syncwarp):
//   load raw[r] = x[t + r*SFIN] (2x128B chunks/instr)
//   pass1: thread j2: a[j1] = raw[16 j1 + j2]; dft16; *w256^{j2 k1};
//          write trans[k1*17 + j2] (region reused)
//   pass2: thread k1=j2: read trans row; dft16 over the 16 j2;
//          write Z[k1 + 16 k2] at [k2*17 + k1]
// ONE __syncthreads, then r12-verified unpack with Zaddr(k)=(k>>4)*17+(k&15).
// Grid 4097 (block 4096 = self-mirror chunk; boundary duplicates identical).
// ---------------------------------------------------------------------------
__device__ __forceinline__ unsigned zaddr(unsigned k) {
    return (k >> 4) * 17u + (k & 15u);
}

__global__ void __launch_bounds__(512, 2) fft256_unpack_warp(
        const float2* __restrict__ x, float* __restrict__ out) {
    extern __shared__ float2 sm[];
    const unsigned tid = threadIdx.x;
    const unsigned w = tid >> 5, lane = tid & 31u;
    const unsigned bb = blockIdx.x;
    const bool isB = (w >= 8u);
    const unsigned w8 = w & 7u;

    // ---- load phase: warp fills its 2 private regions ----
    {
        const unsigned lt = lane & 1u, lr = lane >> 1;       // group-in-warp, r-offset
        const unsigned gloc = 2u * w8 + lt;                  // group index in half
        const unsigned t = isB ? ((SFIN - 16u * bb - 15u + gloc) & (SFIN - 1u))
                               : (16u * bb + gloc);
        const unsigned unit = (isB ? 16u : 0u) + gloc;
        float2* reg = sm + unit * REGION;
#pragma unroll
        for (int it = 0; it < 16; ++it) {
            unsigned r = lr + 16u * (unsigned)it;
            reg[r] = x[t + r * SFIN];
        }
    }
    __syncwarp();

    // ---- FFT phase: half-warp per group, r12-verified radix-16x16 body ----
    {
        const unsigned fg = 2u * w8 + (lane >> 4);           // group for FFT role
        const unsigned funit = (isB ? 16u : 0u) + fg;
        float2* fb = sm + funit * REGION;
        const unsigned j2 = lane & 15u;

        float2 a[16];
#pragma unroll
        for (int j1 = 0; j1 < 16; ++j1)
            a[j1] = fb[16u * (unsigned)j1 + j2];             // raw linear
        __syncwarp();  // all raw reads done before trans overwrite
        dft16(a);
        {
            float2 w1 = c_w256[j2], ww = make_float2(1.f, 0.f);
#pragma unroll
            for (int k1 = 0; k1 < 16; ++k1) {
                fb[(unsigned)k1 * 17u + j2] = cmul(a[k1], ww);
                ww = cmul(ww, w1);
            }
        }
        __syncwarp();
#pragma unroll
        for (int j = 0; j < 16; ++j)
            a[j] = fb[j2 * 17u + (unsigned)j];               // trans row (role k1=j2)
        __syncwarp();  // trans reads done before Z overwrite
        dft16(a);
#pragma unroll
        for (int k2 = 0; k2 < 16; ++k2)
            fb[(unsigned)k2 * 17u + j2] = a[k2];             // Z[j2 + 16 k2]
    }
    __syncthreads();  // Z visible across warps for unpack

    // ---- unpack phase (r12-verified algebra; 512 thr, 8 k's each) ----
    {
        const unsigned gA = tid & 15u;
        const unsigned uu = tid >> 4;            // [0, 32)
        const unsigned t3 = 16u * bb + gA;       // A-group t (< SFIN)
        const float2* gbA = sm + gA * REGION;
        const float2* gbB = sm + (16u + 15u - gA) * REGION;
        const bool tzero = (t3 == 0u);

        float sn, cs;
        __sincosf(-TWO_PI * (float)(t3 + uu * SFIN) * INVN, &sn, &cs);
        float2 W = make_float2(cs, sn);
        const float2 Winc = c_w32[2];            // e^{-2pi i/16}: k += 32 step

#pragma unroll
        for (int j = 0; j < 8; ++j) {
            unsigned k = uu + 32u * (unsigned)j;
            float2 Zk = gbA[zaddr(k)];
            unsigned kp = tzero ? ((256u - k) & 255u) : (255u - k);
            float2 Zm = gbB[zaddr(kp)];

            float2 A = make_float2(0.5f * (Zk.x + Zm.x), 0.5f * (Zk.y - Zm.y));
            float2 C = make_float2(0.5f * (Zk.x - Zm.x), 0.5f * (Zk.y + Zm.y));
            float2 B = make_float2(C.y, -C.x);
            float2 WB = cmul(W, B);
            float2 P = cadd(A, WB);
            float2 Q = csub(A, WB);

            unsigned m = t3 + k * SFIN;              // [0, M)
            unsigned i3 = (NFFT - m) & (NFFT - 1u);  // N - m (mod N)
            unsigned i2 = MFFT - m;
            unsigned i4 = MFFT + m;

            out[m]  = P.x;   out[NFFT + m]  = P.y;
            out[i3] = P.x;   out[NFFT + i3] = -P.y;
            out[i2] = Q.x;   out[NFFT + i2] = -Q.y;
            out[i4] = Q.x;   out[NFFT + i4] = Q.y;

            W = cmul(W, Winc);
        }
    }
}

// ---------------------------------------------------------------------------
// Schedule: P1: z -> D (d_out scratch); P2: D -> B (g_buf); P3U: B -> out.
// P3U reads only g_buf, writes only d_out: no aliasing hazard.
// ---------------------------------------------------------------------------
extern "C" void kernel_launch(void* const* d_in, const int* in_sizes, int n_in,
                              void* d_out, int out_size) {
    const float2* z = (const float2*)d_in[0];   // N reals = M complex (free pack)
    float* out = (float*)d_out;
    float2* D = (float2*)d_out;                 // M float2 scratch fits in out
    float2* B = nullptr;
    cudaGetSymbolAddress((void**)&B, g_buf);

    const size_t smem2 = (size_t)(16u * GS3) * sizeof(float2);    // 65,664 B
    const size_t smem3 = (size_t)(32u * REGION) * sizeof(float2); // 69,888 B
    cudaFuncSetAttribute(fft512_mid,
                         cudaFuncAttributeMaxDynamicSharedMemorySize, (int)smem2);
    cudaFuncSetAttribute(fft256_unpack_warp,
                         cudaFuncAttributeMaxDynamicSharedMemorySize, (int)smem3);

    fft256_first     <<<M256 / 16u, 256>>>(z, D);           // 8192 blocks
    fft512_mid       <<<M512 / 16u, 512, smem2>>>(D, B);    // 4096 blocks
    fft256_unpack_warp<<<NPAIR3, 512, smem3>>>(B, out);     // 4097 blocks
}